// round 10
// baseline (speedup 1.0000x reference)
#include <cuda_runtime.h>
#include <cuda_fp16.h>
#include <cstdint>
#include <cstddef>

// out[h,n,m] = LeakyReLU_{0.2}( sum_d z0[n,d]*z1[m,d]*W[h,d] + bias[h] )
// N=M=1024, D=256, H=128, fp32 in/out.
//
// v10: R9 engine + h-PAIR inner loop (h, h+64) -> 4 independent MMA acc
// chains per warp (kills HMMA RAW stalls), bias preloaded into acc via the
// MMA C operand, branchless LeakyReLU. 3 CTAs/SM, warp tile 16n x 16m x 2h.

#define NT 128

__device__ uint4 g_z0f[64 * 16 * 32];      // [n16tile][ks][lane] {a0,a1,a2,a3}  512KB
__device__ uint4 g_z1f[128 * 8 * 32];      // [m8tile][kspair][lane]             512KB
__device__ uint2 g_wf[128 * 16 * 4];       // [h][ks][c] {w01, w89}              64KB

static constexpr int SM_BIAS = 65536;
static constexpr int SMEM_BYTES = 65536 + 512;

__device__ __forceinline__ uint32_t smem_u32(const void* p) {
    uint32_t a;
    asm("{ .reg .u64 t; cvta.to.shared.u64 t, %1; cvt.u32.u64 %0, t; }" : "=r"(a) : "l"(p));
    return a;
}

#define CP16(saddr, gptr)                                                     \
    asm volatile("cp.async.cg.shared.global [%0], [%1], 16;"                  \
                 :: "r"(saddr), "l"(gptr))

#define MMA(c, a0, a1, a2, a3, b0, b1)                                        \
    asm volatile("mma.sync.aligned.m16n8k16.row.col.f32.f16.f16.f32 "         \
                 "{%0,%1,%2,%3}, {%4,%5,%6,%7}, {%8,%9}, {%0,%1,%2,%3};"      \
                 : "+f"((c)[0]), "+f"((c)[1]), "+f"((c)[2]), "+f"((c)[3])     \
                 : "r"(a0), "r"(a1), "r"(a2), "r"(a3), "r"(b0), "r"(b1))

#define HMUL2(d, x, y)                                                        \
    asm("mul.f16x2 %0, %1, %2;" : "=r"(d) : "r"(x), "r"(y))

#define LDS_W(w0, w1, addr)                                                   \
    asm("ld.shared.v2.b32 {%0,%1}, [%2];" : "=r"(w0), "=r"(w1) : "r"(addr))

// ---------------- prep kernels ----------------

__global__ void prep_z0f(const float* __restrict__ z0) {
    int gid = blockIdx.x * 256 + threadIdx.x;      // 32768 threads
    int t_n = gid >> 9, ks = (gid >> 5) & 15, lane = gid & 31;
    int n = t_n * 16 + (lane >> 2);
    int k0 = ks * 16 + (lane & 3) * 2;
    const float* r0 = z0 + (size_t)n * 256;
    const float* r8 = r0 + 8 * 256;
    float2 p0 = *(const float2*)(r0 + k0);
    float2 p1 = *(const float2*)(r8 + k0);
    float2 p2 = *(const float2*)(r0 + k0 + 8);
    float2 p3 = *(const float2*)(r8 + k0 + 8);
    union { __half2 h[4]; uint4 u; } pk;
    pk.h[0] = __floats2half2_rn(p0.x, p0.y);
    pk.h[1] = __floats2half2_rn(p1.x, p1.y);
    pk.h[2] = __floats2half2_rn(p2.x, p2.y);
    pk.h[3] = __floats2half2_rn(p3.x, p3.y);
    g_z0f[gid] = pk.u;
}

__global__ void prep_z1f(const float* __restrict__ z1) {
    int gid = blockIdx.x * 256 + threadIdx.x;      // 32768 threads
    int t8 = gid >> 8, ksp = (gid >> 5) & 7, lane = gid & 31;
    int m = t8 * 8 + (lane >> 2);
    int ka = ksp * 32 + (lane & 3) * 2;
    const float* r = z1 + (size_t)m * 256;
    float2 a0 = *(const float2*)(r + ka);
    float2 a1 = *(const float2*)(r + ka + 8);
    float2 b0 = *(const float2*)(r + ka + 16);
    float2 b1 = *(const float2*)(r + ka + 24);
    union { __half2 h[4]; uint4 u; } pk;
    pk.h[0] = __floats2half2_rn(a0.x, a0.y);
    pk.h[1] = __floats2half2_rn(a1.x, a1.y);
    pk.h[2] = __floats2half2_rn(b0.x, b0.y);
    pk.h[3] = __floats2half2_rn(b1.x, b1.y);
    g_z1f[gid] = pk.u;
}

__global__ void prep_wf(const float* __restrict__ W) {
    int gid = blockIdx.x * 256 + threadIdx.x;      // 8192 threads
    int h = gid >> 6, ks = (gid >> 2) & 15, c = gid & 3;
    int k0 = ks * 16 + c * 2;
    const float* r = W + (size_t)h * 256;
    float2 p0 = *(const float2*)(r + k0);
    float2 p1 = *(const float2*)(r + k0 + 8);
    union { __half2 h2[2]; uint2 u; } pk;
    pk.h2[0] = __floats2half2_rn(p0.x, p0.y);
    pk.h2[1] = __floats2half2_rn(p1.x, p1.y);
    g_wf[gid] = pk.u;
}

// ---------------- main kernel ----------------

__global__ void __launch_bounds__(NT, 3)
fc_main(const float* __restrict__ bias, float* __restrict__ out)
{
    extern __shared__ char smem[];
    const uint32_t sbase = smem_u32(smem);
    const int tid = threadIdx.x;
    const int wid = tid >> 5;      // 0..3 = 16m slab
    const int lid = tid & 31;

    const int ms = (int)(blockIdx.x & 15);    // m-supertile (64 m)
    const int nt = (int)(blockIdx.x >> 4);    // n-tile (16 n), 0..63

    // Stage W-frag table (64KB) + bias (512B) into smem
    {
        const uint4* gw = reinterpret_cast<const uint4*>(g_wf);
        #pragma unroll
        for (int i = 0; i < 32; ++i)
            CP16(sbase + (uint32_t)((tid + i * 128) * 16), gw + tid + i * 128);
        if (tid < 32)
            CP16(sbase + SM_BIAS + (uint32_t)(tid * 16),
                 reinterpret_cast<const uint4*>(bias) + tid);
        asm volatile("cp.async.commit_group;" ::: "memory");
    }

    // Persistent fragments: z0 (64 regs), z1 (64 regs)
    uint4 z0f[16];
    {
        const uint4* p = g_z0f + ((size_t)nt * 16) * 32 + lid;
        #pragma unroll
        for (int ks = 0; ks < 16; ++ks) z0f[ks] = p[ks * 32];
    }
    uint4 z1p[2][8];
    {
        #pragma unroll
        for (int u = 0; u < 2; ++u) {
            const uint4* p = g_z1f + ((size_t)(ms * 8 + wid * 2 + u) * 8) * 32 + lid;
            #pragma unroll
            for (int kp = 0; kp < 8; ++kp) z1p[u][kp] = p[kp * 32];
        }
    }

    asm volatile("cp.async.wait_group 0;" ::: "memory");
    __syncthreads();

    const uint32_t wlane = sbase + (uint32_t)((lid & 3) * 8);
    const int n_lo = nt * 16 + (lid >> 2);
    const int mb   = ms * 64 + wid * 16 + (lid & 3) * 2;
    const size_t obase = (size_t)n_lo * 1024 + mb;

    // Per-warp/CTA stagger over the 64 h-pairs.
    const int hb = (((int)blockIdx.x << 3) + (wid << 4)) & 63;

    #pragma unroll 1
    for (int i = 0; i < 64; ++i) {
        const int hA = (i + hb) & 63;      // pair = (hA, hA+64)
        const uint32_t wbA = wlane + (uint32_t)(hA * 512);
        const uint32_t wbB = wbA + 64 * 512;

        // acc init = bias (MMA C operand carries it; epilogue FADD deleted)
        float bvA, bvB;
        asm("ld.shared.f32 %0, [%1];" : "=f"(bvA) : "r"(sbase + SM_BIAS + (uint32_t)(hA * 4)));
        asm("ld.shared.f32 %0, [%1];" : "=f"(bvB) : "r"(sbase + SM_BIAS + (uint32_t)(hA * 4 + 256)));
        float acc[2][2][4];
        #pragma unroll
        for (int u = 0; u < 2; ++u)
            #pragma unroll
            for (int q = 0; q < 4; ++q) { acc[0][u][q] = bvA; acc[1][u][q] = bvB; }

        // W ring, depth 1 (preload ks=0 for both h)
        uint32_t wA0, wA1, wB0, wB1;
        LDS_W(wA0, wA1, wbA);
        LDS_W(wB0, wB1, wbB);

        #pragma unroll
        for (int ks = 0; ks < 16; ++ks) {
            uint32_t nA0 = wA0, nA1 = wA1, nB0 = wB0, nB1 = wB1;
            if (ks < 15) {
                LDS_W(nA0, nA1, wbA + (uint32_t)((ks + 1) * 32));
                LDS_W(nB0, nB1, wbB + (uint32_t)((ks + 1) * 32));
            }
            const uint32_t b0l = (ks & 1) ? z1p[0][ks >> 1].z : z1p[0][ks >> 1].x;
            const uint32_t b1l = (ks & 1) ? z1p[0][ks >> 1].w : z1p[0][ks >> 1].y;
            const uint32_t b0h = (ks & 1) ? z1p[1][ks >> 1].z : z1p[1][ks >> 1].x;
            const uint32_t b1h = (ks & 1) ? z1p[1][ks >> 1].w : z1p[1][ks >> 1].y;
            {
                uint32_t a0, a1, a2, a3;
                HMUL2(a0, z0f[ks].x, wA0);
                HMUL2(a1, z0f[ks].y, wA0);
                HMUL2(a2, z0f[ks].z, wA1);
                HMUL2(a3, z0f[ks].w, wA1);
                MMA(acc[0][0], a0, a1, a2, a3, b0l, b1l);
                MMA(acc[0][1], a0, a1, a2, a3, b0h, b1h);
            }
            {
                uint32_t a0, a1, a2, a3;
                HMUL2(a0, z0f[ks].x, wB0);
                HMUL2(a1, z0f[ks].y, wB0);
                HMUL2(a2, z0f[ks].z, wB1);
                HMUL2(a3, z0f[ks].w, wB1);
                MMA(acc[1][0], a0, a1, a2, a3, b0l, b1l);
                MMA(acc[1][1], a0, a1, a2, a3, b0h, b1h);
            }
            wA0 = nA0; wA1 = nA1; wB0 = nB0; wB1 = nB1;
        }

        // Epilogue: branchless LeakyReLU + STG.64 streaming (bias already in)
        #pragma unroll
        for (int hh = 0; hh < 2; ++hh) {
            float* ob = out + (((size_t)(hA + hh * 64)) << 20) + obase;
            #pragma unroll
            for (int u = 0; u < 2; ++u) {
                float2 lo, hi;
                lo.x = fmaxf(acc[hh][u][0], 0.f) + 0.2f * fminf(acc[hh][u][0], 0.f);
                lo.y = fmaxf(acc[hh][u][1], 0.f) + 0.2f * fminf(acc[hh][u][1], 0.f);
                hi.x = fmaxf(acc[hh][u][2], 0.f) + 0.2f * fminf(acc[hh][u][2], 0.f);
                hi.y = fmaxf(acc[hh][u][3], 0.f) + 0.2f * fminf(acc[hh][u][3], 0.f);
                __stcs(reinterpret_cast<float2*>(ob + u * 8), lo);
                __stcs(reinterpret_cast<float2*>(ob + 8 * 1024 + u * 8), hi);
            }
        }
    }
}

extern "C" void kernel_launch(void* const* d_in, const int* in_sizes, int n_in,
                              void* d_out, int out_size) {
    const float* z0   = (const float*)d_in[0];   // (1, 1024, 256)
    const float* z1   = (const float*)d_in[1];   // (1, 1024, 256)
    const float* W    = (const float*)d_in[2];   // (128, 256)
    const float* bias = (const float*)d_in[3];   // (128,)
    float* out = (float*)d_out;                  // (1, 128, 1024, 1024)

    prep_z0f<<<128, 256>>>(z0);
    prep_z1f<<<128, 256>>>(z1);
    prep_wf<<<32, 256>>>(W);

    cudaFuncSetAttribute(fc_main, cudaFuncAttributeMaxDynamicSharedMemorySize, SMEM_BYTES);
    // grid: 64 nt x 16 ms = 1024 CTAs
    fc_main<<<1024, NT, SMEM_BYTES>>>(bias, out);
}

// round 11
// speedup vs baseline: 1.0323x; 1.0323x over previous
#include <cuda_runtime.h>
#include <cuda_fp16.h>
#include <cstdint>
#include <cstddef>

// out[h,n,m] = LeakyReLU_{0.2}( sum_d z0[n,d]*z1[m,d]*W[h,d] + bias[h] )
// N=M=1024, D=256, H=128, fp32 in/out.
//
// v11: R9 engine + h-split-8 for 97% wave packing.
//  - CTA = 16n x 64m x 16h; grid = 64nt x 16ms x 8hs = 8192 CTAs (~19 waves
//    over 444 co-resident slots -> 97% packing vs 77% at grid 1024).
//  - z0/z1 fragments register-resident; 8KB W-frag slice + bias in smem.
//  - bias preloaded into MMA accumulator; LeakyReLU = fmax(x, 0.2x);
//    depth-2 W LDS ring.

#define NT 128

__device__ uint4 g_z0f[64 * 16 * 32];      // [n16tile][ks][lane] {a0,a1,a2,a3}  512KB
__device__ uint4 g_z1f[128 * 8 * 32];      // [m8tile][kspair][lane]             512KB
__device__ uint2 g_wf[128 * 16 * 4];       // [h][ks][c] {w01, w89}              64KB

static constexpr int SM_BIAS = 8192;                // after 8KB W slice
static constexpr int SMEM_BYTES = 8192 + 256;

__device__ __forceinline__ uint32_t smem_u32(const void* p) {
    uint32_t a;
    asm("{ .reg .u64 t; cvta.to.shared.u64 t, %1; cvt.u32.u64 %0, t; }" : "=r"(a) : "l"(p));
    return a;
}

#define CP16(saddr, gptr)                                                     \
    asm volatile("cp.async.cg.shared.global [%0], [%1], 16;"                  \
                 :: "r"(saddr), "l"(gptr))

#define MMA(c, a0, a1, a2, a3, b0, b1)                                        \
    asm volatile("mma.sync.aligned.m16n8k16.row.col.f32.f16.f16.f32 "         \
                 "{%0,%1,%2,%3}, {%4,%5,%6,%7}, {%8,%9}, {%0,%1,%2,%3};"      \
                 : "+f"((c)[0]), "+f"((c)[1]), "+f"((c)[2]), "+f"((c)[3])     \
                 : "r"(a0), "r"(a1), "r"(a2), "r"(a3), "r"(b0), "r"(b1))

#define HMUL2(d, x, y)                                                        \
    asm("mul.f16x2 %0, %1, %2;" : "=r"(d) : "r"(x), "r"(y))

#define LDS_W(w0, w1, addr)                                                   \
    asm("ld.shared.v2.b32 {%0,%1}, [%2];" : "=r"(w0), "=r"(w1) : "r"(addr))

// ---------------- prep kernels ----------------

__global__ void prep_z0f(const float* __restrict__ z0) {
    int gid = blockIdx.x * 256 + threadIdx.x;      // 32768 threads
    int t_n = gid >> 9, ks = (gid >> 5) & 15, lane = gid & 31;
    int n = t_n * 16 + (lane >> 2);
    int k0 = ks * 16 + (lane & 3) * 2;
    const float* r0 = z0 + (size_t)n * 256;
    const float* r8 = r0 + 8 * 256;
    float2 p0 = *(const float2*)(r0 + k0);
    float2 p1 = *(const float2*)(r8 + k0);
    float2 p2 = *(const float2*)(r0 + k0 + 8);
    float2 p3 = *(const float2*)(r8 + k0 + 8);
    union { __half2 h[4]; uint4 u; } pk;
    pk.h[0] = __floats2half2_rn(p0.x, p0.y);
    pk.h[1] = __floats2half2_rn(p1.x, p1.y);
    pk.h[2] = __floats2half2_rn(p2.x, p2.y);
    pk.h[3] = __floats2half2_rn(p3.x, p3.y);
    g_z0f[gid] = pk.u;
}

__global__ void prep_z1f(const float* __restrict__ z1) {
    int gid = blockIdx.x * 256 + threadIdx.x;      // 32768 threads
    int t8 = gid >> 8, ksp = (gid >> 5) & 7, lane = gid & 31;
    int m = t8 * 8 + (lane >> 2);
    int ka = ksp * 32 + (lane & 3) * 2;
    const float* r = z1 + (size_t)m * 256;
    float2 a0 = *(const float2*)(r + ka);
    float2 a1 = *(const float2*)(r + ka + 8);
    float2 b0 = *(const float2*)(r + ka + 16);
    float2 b1 = *(const float2*)(r + ka + 24);
    union { __half2 h[4]; uint4 u; } pk;
    pk.h[0] = __floats2half2_rn(a0.x, a0.y);
    pk.h[1] = __floats2half2_rn(a1.x, a1.y);
    pk.h[2] = __floats2half2_rn(b0.x, b0.y);
    pk.h[3] = __floats2half2_rn(b1.x, b1.y);
    g_z1f[gid] = pk.u;
}

__global__ void prep_wf(const float* __restrict__ W) {
    int gid = blockIdx.x * 256 + threadIdx.x;      // 8192 threads
    int h = gid >> 6, ks = (gid >> 2) & 15, c = gid & 3;
    int k0 = ks * 16 + c * 2;
    const float* r = W + (size_t)h * 256;
    float2 p0 = *(const float2*)(r + k0);
    float2 p1 = *(const float2*)(r + k0 + 8);
    union { __half2 h2[2]; uint2 u; } pk;
    pk.h2[0] = __floats2half2_rn(p0.x, p0.y);
    pk.h2[1] = __floats2half2_rn(p1.x, p1.y);
    g_wf[gid] = pk.u;
}

// ---------------- main kernel ----------------

__global__ void __launch_bounds__(NT, 3)
fc_main(const float* __restrict__ bias, float* __restrict__ out)
{
    extern __shared__ char smem[];
    const uint32_t sbase = smem_u32(smem);
    const int tid = threadIdx.x;
    const int wid = tid >> 5;      // 0..3 = 16m slab
    const int lid = tid & 31;

    const int bid = (int)blockIdx.x;
    const int nt = bid & 63;            // n-tile (16 n)
    const int ms = (bid >> 6) & 15;     // m-supertile (64 m)
    const int h0 = (bid >> 10) << 4;    // h-slice base (16 h)

    // Stage W-frag slice (8KB for h0..h0+15) + bias slice (64B)
    {
        const uint4* gw = reinterpret_cast<const uint4*>(g_wf + (size_t)h0 * 64);
        #pragma unroll
        for (int i = 0; i < 4; ++i)
            CP16(sbase + (uint32_t)((tid + i * 128) * 16), gw + tid + i * 128);
        if (tid < 4)
            CP16(sbase + SM_BIAS + (uint32_t)(tid * 16),
                 reinterpret_cast<const uint4*>(bias + h0) + tid);
        asm volatile("cp.async.commit_group;" ::: "memory");
    }

    // Persistent fragments: z0 (64 regs), z1 (64 regs)
    uint4 z0f[16];
    {
        const uint4* p = g_z0f + ((size_t)nt * 16) * 32 + lid;
        #pragma unroll
        for (int ks = 0; ks < 16; ++ks) z0f[ks] = p[ks * 32];
    }
    uint4 z1p[2][8];
    {
        #pragma unroll
        for (int u = 0; u < 2; ++u) {
            const uint4* p = g_z1f + ((size_t)(ms * 8 + wid * 2 + u) * 8) * 32 + lid;
            #pragma unroll
            for (int kp = 0; kp < 8; ++kp) z1p[u][kp] = p[kp * 32];
        }
    }

    asm volatile("cp.async.wait_group 0;" ::: "memory");
    __syncthreads();

    const uint32_t wlane = sbase + (uint32_t)((lid & 3) * 8);
    const int n_lo = nt * 16 + (lid >> 2);
    const int mb   = ms * 64 + wid * 16 + (lid & 3) * 2;
    const size_t obase = (size_t)n_lo * 1024 + mb;

    // Stagger the 16 h's across warps and co-resident CTAs.
    const int hb = ((wid << 2) | (bid & 3)) & 15;

    #pragma unroll 1
    for (int i = 0; i < 16; ++i) {
        const int hh = (i + hb) & 15;                 // slice-local h
        const uint32_t wbase = wlane + (uint32_t)(hh * 512);

        // acc init = bias (carried through the MMA C operand)
        float bv;
        asm("ld.shared.f32 %0, [%1];" : "=f"(bv) : "r"(sbase + SM_BIAS + (uint32_t)(hh * 4)));
        float acc[2][4];
        #pragma unroll
        for (int u = 0; u < 2; ++u)
            #pragma unroll
            for (int q = 0; q < 4; ++q) acc[u][q] = bv;

        // depth-2 W ring
        uint32_t w00, w01, w10, w11;
        LDS_W(w00, w01, wbase);
        LDS_W(w10, w11, wbase + 32);

        #pragma unroll
        for (int ks = 0; ks < 16; ++ks) {
            uint32_t wn0 = w10, wn1 = w11;
            if (ks < 14)
                LDS_W(wn0, wn1, wbase + (uint32_t)((ks + 2) * 32));
            uint32_t a0, a1, a2, a3;
            HMUL2(a0, z0f[ks].x, w00);
            HMUL2(a1, z0f[ks].y, w00);
            HMUL2(a2, z0f[ks].z, w01);
            HMUL2(a3, z0f[ks].w, w01);
            #pragma unroll
            for (int u = 0; u < 2; ++u) {
                const uint32_t b0 = (ks & 1) ? z1p[u][ks >> 1].z : z1p[u][ks >> 1].x;
                const uint32_t b1 = (ks & 1) ? z1p[u][ks >> 1].w : z1p[u][ks >> 1].y;
                MMA(acc[u], a0, a1, a2, a3, b0, b1);
            }
            w00 = w10; w01 = w11;
            w10 = wn0; w11 = wn1;
        }

        // Epilogue: LeakyReLU = max(x, 0.2x); bias already in acc.
        float* ob = out + (((size_t)(h0 + hh)) << 20) + obase;
        #pragma unroll
        for (int u = 0; u < 2; ++u) {
            float2 lo, hi;
            lo.x = fmaxf(acc[u][0], 0.2f * acc[u][0]);
            lo.y = fmaxf(acc[u][1], 0.2f * acc[u][1]);
            hi.x = fmaxf(acc[u][2], 0.2f * acc[u][2]);
            hi.y = fmaxf(acc[u][3], 0.2f * acc[u][3]);
            __stcs(reinterpret_cast<float2*>(ob + u * 8), lo);
            __stcs(reinterpret_cast<float2*>(ob + 8 * 1024 + u * 8), hi);
        }
    }
}

extern "C" void kernel_launch(void* const* d_in, const int* in_sizes, int n_in,
                              void* d_out, int out_size) {
    const float* z0   = (const float*)d_in[0];   // (1, 1024, 256)
    const float* z1   = (const float*)d_in[1];   // (1, 1024, 256)
    const float* W    = (const float*)d_in[2];   // (128, 256)
    const float* bias = (const float*)d_in[3];   // (128,)
    float* out = (float*)d_out;                  // (1, 128, 1024, 1024)

    prep_z0f<<<128, 256>>>(z0);
    prep_z1f<<<128, 256>>>(z1);
    prep_wf<<<32, 256>>>(W);

    cudaFuncSetAttribute(fc_main, cudaFuncAttributeMaxDynamicSharedMemorySize, SMEM_BYTES);
    // grid: 64 nt x 16 ms x 8 hs = 8192 CTAs
    fc_main<<<8192, NT, SMEM_BYTES>>>(bias, out);
}